// round 4
// baseline (speedup 1.0000x reference)
#include <cuda_runtime.h>
#include <math.h>

// ---------------------------------------------------------------------------
// QRNN: h_t = tanh(x_t @ Wh + b + h_{t-1} @ Uh),  T=512, B=32, D=1024
// f32x2 packed-FMA everywhere; recurrence uses per-tile dataflow flags.
// ---------------------------------------------------------------------------

#define TT 512
#define BB 32
#define DD 1024
#define QQ 256

#define HST 1028          // hs row stride (floats)
#define USTP 33           // Usp row stride (float2 per k-pair)
#define PSTR 264          // part warp stride (floats)

__device__ float g_Wh[DD * DD];
__device__ float g_Uh[DD * DD];
__device__ int   g_flag[TT][4][32];   // per (t, batch-group, ntile) flag

// ------------------------- f32x2 helpers ------------------------------------
__device__ __forceinline__ void fma2(unsigned long long& d,
                                     unsigned long long a, unsigned long long b) {
    asm("fma.rn.f32x2 %0, %1, %2, %0;" : "+l"(d) : "l"(a), "l"(b));
}
__device__ __forceinline__ float unpack_sum(unsigned long long v) {
    float lo, hi;
    asm("mov.b64 {%0, %1}, %2;" : "=f"(lo), "=f"(hi) : "l"(v));
    return lo + hi;
}

// ------------------------- sync primitives ----------------------------------
__device__ __forceinline__ int ld_acq(const int* p) {
    int v;
    asm volatile("ld.acquire.gpu.global.s32 %0, [%1];" : "=r"(v) : "l"(p) : "memory");
    return v;
}
__device__ __forceinline__ void st_rel(int* p, int v) {
    asm volatile("st.release.gpu.global.s32 [%0], %1;" :: "l"(p), "r"(v) : "memory");
}

// --------------------------- flag reset -------------------------------------
__global__ void zero_flags_kernel() {
    int i = blockIdx.x * blockDim.x + threadIdx.x;
    if (i < TT * 4 * 32) (&g_flag[0][0][0])[i] = 0;
}

// --------------------------- quaternion matrix build ------------------------
__global__ void build_qmat_kernel(const float* __restrict__ wr,
                                  const float* __restrict__ wi,
                                  const float* __restrict__ wj,
                                  const float* __restrict__ wk,
                                  int which) {
    int e = blockIdx.x * blockDim.x + threadIdx.x;
    int d = blockIdx.y;
    int br = d >> 8, bc = e >> 8;
    int r = d & 255, c = e & 255;
    int comp = br ^ bc;
    int mask = (0x5390 >> (br * 4)) & 0xF;
    float s = ((mask >> bc) & 1) ? -1.0f : 1.0f;
    const float* w = (comp == 0) ? wr : (comp == 1) ? wi : (comp == 2) ? wj : wk;
    float* W = which ? g_Uh : g_Wh;
    W[d * DD + e] = s * w[r * QQ + c];
}

// --------------------------- SGEMM with FFMA2 -------------------------------
#define GBM 128
#define GBN 128
#define GBK 8

__global__ void __launch_bounds__(256)
sgemm_bias_kernel(const float* __restrict__ A, const float* __restrict__ bias,
                  float* __restrict__ C, int M, int N, int K) {
    __shared__ float2 As2[2][GBK][GBM];   // duplicated pairs (v,v)
    __shared__ float  Bs[2][GBK][GBN];
    const float* Bmat = g_Wh;

    int tid  = threadIdx.x;
    int brow = blockIdx.y, bcol = blockIdx.x;
    int arow = tid >> 1,  acol = (tid & 1) << 2;
    int brl  = tid >> 5,  bcl  = (tid & 31) << 2;

    const float* Ab = A + (size_t)(brow * GBM) * K;
    const float* Bb = Bmat + bcol * GBN;

    float4 av = *(const float4*)&Ab[(size_t)arow * K + acol];
    float4 bv = *(const float4*)&Bb[(size_t)brl * N + bcl];
    As2[0][acol + 0][arow] = make_float2(av.x, av.x);
    As2[0][acol + 1][arow] = make_float2(av.y, av.y);
    As2[0][acol + 2][arow] = make_float2(av.z, av.z);
    As2[0][acol + 3][arow] = make_float2(av.w, av.w);
    *(float4*)&Bs[0][brl][bcl] = bv;
    __syncthreads();

    int tm = (tid >> 4) << 3;
    int tn = (tid & 15) << 3;
    unsigned long long acc2[8][4];
#pragma unroll
    for (int i = 0; i < 8; i++)
#pragma unroll
        for (int j = 0; j < 4; j++) acc2[i][j] = 0ULL;

    int nk = K / GBK;
    for (int kt = 0; kt < nk; ++kt) {
        int cur = kt & 1;
        float4 an, bn;
        if (kt + 1 < nk) {
            an = *(const float4*)&Ab[(size_t)arow * K + (kt + 1) * GBK + acol];
            bn = *(const float4*)&Bb[(size_t)((kt + 1) * GBK + brl) * N + bcl];
        }
#pragma unroll
        for (int kk = 0; kk < GBK; kk++) {
            ulonglong2 ra01 = *(const ulonglong2*)&As2[cur][kk][tm];
            ulonglong2 ra23 = *(const ulonglong2*)&As2[cur][kk][tm + 2];
            ulonglong2 ra45 = *(const ulonglong2*)&As2[cur][kk][tm + 4];
            ulonglong2 ra67 = *(const ulonglong2*)&As2[cur][kk][tm + 6];
            ulonglong2 rb03 = *(const ulonglong2*)&Bs[cur][kk][tn];
            ulonglong2 rb47 = *(const ulonglong2*)&Bs[cur][kk][tn + 4];
            unsigned long long ra[8] = {ra01.x, ra01.y, ra23.x, ra23.y,
                                        ra45.x, ra45.y, ra67.x, ra67.y};
            unsigned long long rb[4] = {rb03.x, rb03.y, rb47.x, rb47.y};
#pragma unroll
            for (int i = 0; i < 8; i++)
#pragma unroll
                for (int j = 0; j < 4; j++) fma2(acc2[i][j], ra[i], rb[j]);
        }
        if (kt + 1 < nk) {
            int nxt = cur ^ 1;
            As2[nxt][acol + 0][arow] = make_float2(an.x, an.x);
            As2[nxt][acol + 1][arow] = make_float2(an.y, an.y);
            As2[nxt][acol + 2][arow] = make_float2(an.z, an.z);
            As2[nxt][acol + 3][arow] = make_float2(an.w, an.w);
            *(float4*)&Bs[nxt][brl][bcl] = bn;
            __syncthreads();
        }
    }

    float bias_r[8];
#pragma unroll
    for (int j = 0; j < 8; j++) bias_r[j] = bias[bcol * GBN + tn + j];
#pragma unroll
    for (int i = 0; i < 8; i++) {
        float c_[8];
#pragma unroll
        for (int j = 0; j < 4; j++) {
            float lo, hi;
            asm("mov.b64 {%0, %1}, %2;" : "=f"(lo), "=f"(hi) : "l"(acc2[i][j]));
            c_[2 * j]     = lo + bias_r[2 * j];
            c_[2 * j + 1] = hi + bias_r[2 * j + 1];
        }
        size_t row = (size_t)(brow * GBM + tm + i) * N + bcol * GBN + tn;
        *(float4*)&C[row]     = *(float4*)&c_[0];
        *(float4*)&C[row + 4] = *(float4*)&c_[4];
    }
}

// --------------------------- recurrence -------------------------------------
// CTA (n,g): tile rows [g*8,g*8+8) x cols [n*32,n*32+32), full K=1024.
// Uh slab pair-major in SMEM: Usp[k/2][c] = (Uh[2k'][C+c], Uh[2k'+1][C+c]).
// 8 warps split K (128 each). Per-warp dataflow: spin on 4 producer-tile
// flags, stage private h slice (syncwarp only), FFMA2 k-paired inner loop,
// SMEM split-K reduce (2 CTA syncs), tanh, STG, release own tile flag.
__global__ void __launch_bounds__(256)
recur_kernel(float* __restrict__ out) {
    extern __shared__ float sm[];
    float2* Usp = (float2*)sm;                        // [512][USTP]
    float*  hs  = sm + 512 * USTP * 2;                // [8][HST]
    float*  part = hs + 8 * HST;                      // [8][PSTR]

    int tid = threadIdx.x;
    int n = blockIdx.x >> 2;      // ntile 0..31
    int g = blockIdx.x & 3;       // batch group 0..3

    // load + pair-transpose Uh column slab
    for (int i = tid; i < 1024 * 8; i += 256) {
        int k = i >> 3, c4 = (i & 7) << 2;
        float4 v = *(const float4*)&g_Uh[(size_t)k * DD + n * 32 + c4];
        int k2 = k >> 1, half = k & 1;
        float* base = (float*)&Usp[k2 * USTP + c4];
        base[0 + half] = v.x;
        base[2 + half] = v.y;
        base[4 + half] = v.z;
        base[6 + half] = v.w;
    }

    int ob = tid >> 5, oc = tid & 31;
    size_t obase = (size_t)(g * 8 + ob) * DD + n * 32 + oc;

    // t = 0
    float v0 = out[obase];
    __syncthreads();
    out[obase] = tanhf(v0);
    __syncthreads();
    if (tid == 0) { __threadfence(); st_rel(&g_flag[0][g][n], 1); }

    int lane = tid & 31, w = tid >> 5;
    int bg = (lane >> 3) << 1;     // rows bg, bg+1
    int cg = lane & 7;             // cols cg + 8*jj
    int kb = w << 7;

    for (int t = 1; t < TT; ++t) {
        float whv = __ldcg(&out[(size_t)t * BB * DD + obase]);

        // warp-level spin: 4 producer tiles covering k-slice [kb, kb+128)
        int rdy = (lane < 4) ? 0 : 1;
        while (!__all_sync(0xffffffffu, rdy)) {
            if (!rdy) rdy = (ld_acq(&g_flag[t - 1][g][(w << 2) + lane]) != 0);
        }

        // stage private h slice: rows 0..7 x cols [kb, kb+128)
        const float* hrow = out + (size_t)(t - 1) * BB * DD
                          + (size_t)(g * 8) * DD + kb;
#pragma unroll
        for (int r = 0; r < 8; ++r) {
            float4 hv = *(const float4*)&hrow[(size_t)r * DD + (lane << 2)];
            *(float4*)&hs[r * HST + kb + (lane << 2)] = hv;
        }
        __syncwarp();

        unsigned long long acc[2][4];
#pragma unroll
        for (int r = 0; r < 2; ++r)
#pragma unroll
            for (int j = 0; j < 4; ++j) acc[r][j] = 0ULL;

        const float* h0b = &hs[bg * HST + kb];
        const float* h1b = &hs[(bg + 1) * HST + kb];
        const float2* ub = &Usp[(kb >> 1) * USTP + cg];

#pragma unroll 8
        for (int kk = 0; kk < 128; kk += 4) {
            ulonglong2 h0 = *(const ulonglong2*)&h0b[kk];
            ulonglong2 h1 = *(const ulonglong2*)&h1b[kk];
            const float2* u0p = ub + (kk >> 1) * USTP;
            const float2* u1p = u0p + USTP;
#pragma unroll
            for (int jj = 0; jj < 4; ++jj) {
                unsigned long long u0 = *(const unsigned long long*)(u0p + (jj << 3));
                unsigned long long u1 = *(const unsigned long long*)(u1p + (jj << 3));
                fma2(acc[0][jj], h0.x, u0);
                fma2(acc[0][jj], h0.y, u1);
                fma2(acc[1][jj], h1.x, u0);
                fma2(acc[1][jj], h1.y, u1);
            }
        }

        // split-K partials -> SMEM
#pragma unroll
        for (int r = 0; r < 2; ++r)
#pragma unroll
            for (int jj = 0; jj < 4; ++jj)
                part[w * PSTR + (bg + r) * 32 + cg + (jj << 3)] = unpack_sum(acc[r][jj]);
        __syncthreads();

        float s = whv;
#pragma unroll
        for (int ww = 0; ww < 8; ++ww) s += part[ww * PSTR + tid];
        out[(size_t)t * BB * DD + obase] = tanhf(s);
        __syncthreads();
        if (tid == 0) { __threadfence(); st_rel(&g_flag[t][g][n], 1); }
    }
}

// --------------------------- launch ------------------------------------------
extern "C" void kernel_launch(void* const* d_in, const int* in_sizes, int n_in,
                              void* d_out, int out_size) {
    const float* x    = (const float*)d_in[0];
    const float* wh_r = (const float*)d_in[1];
    const float* wh_i = (const float*)d_in[2];
    const float* wh_j = (const float*)d_in[3];
    const float* wh_k = (const float*)d_in[4];
    const float* uh_r = (const float*)d_in[5];
    const float* uh_i = (const float*)d_in[6];
    const float* uh_j = (const float*)d_in[7];
    const float* uh_k = (const float*)d_in[8];
    const float* wh_b = (const float*)d_in[9];
    float* out = (float*)d_out;

    zero_flags_kernel<<<(TT * 4 * 32 + 255) / 256, 256>>>();

    dim3 bq(DD / 256, DD);
    build_qmat_kernel<<<bq, 256>>>(wh_r, wh_i, wh_j, wh_k, 0);
    build_qmat_kernel<<<bq, 256>>>(uh_r, uh_i, uh_j, uh_k, 1);

    dim3 gg(DD / GBN, (TT * BB) / GBM);   // (8, 128)
    sgemm_bias_kernel<<<gg, 256>>>(x, wh_b, out, TT * BB, DD, DD);

    const int smem_bytes = (512 * USTP * 2 + 8 * HST + 8 * PSTR) * 4;
    cudaFuncSetAttribute(recur_kernel,
                         cudaFuncAttributeMaxDynamicSharedMemorySize, smem_bytes);
    recur_kernel<<<32 * 4, 256, smem_bytes>>>(out);
}